// round 8
// baseline (speedup 1.0000x reference)
#include <cuda_runtime.h>

#define NS 512       // sequence length N
#define DD 64        // feature dim d
#define NB 64        // batch B
#define GTJ 64       // column tiles (8 wide each)
#define NDIAG 192    // max kd = 190 (B of thread 63), padded even
#define C2_NEG (-0x40000000)
#define SHIFT 90     // prescale: align tile inputs near 2^90 for headroom

// 64 MB scratch: E[b,i,j] = exp(-||x_i - y_j||)
__device__ float g_E[(size_t)NB * NS * NS];

// ---------------------------------------------------------------------------
// Packed f32x2 FMA (Blackwell)
// ---------------------------------------------------------------------------
__device__ __forceinline__ void fma2(unsigned long long& d,
                                     unsigned long long a,
                                     unsigned long long b) {
    asm("fma.rn.f32x2 %0, %1, %2, %0;" : "+l"(d) : "l"(a), "l"(b));
}

// ---------------------------------------------------------------------------
// Stage 1: E[b,i,j] = exp(-sqrt(max(0, |x_i|^2 + |y_j|^2 - 2 x_i.y_j)))
// (unchanged — stage 2 is the bottleneck)
// ---------------------------------------------------------------------------
__global__ void __launch_bounds__(256, 2)
cdist_kernel(const float* __restrict__ X, const float* __restrict__ Y) {
    __shared__ float Xs[64 * 64];
    __shared__ float Ys[64 * 64];
    __shared__ float xn[64], yn[64];

    const int b  = blockIdx.z;
    const int i0 = blockIdx.y * 64;
    const int j0 = blockIdx.x * 64;
    const int tid = threadIdx.y * 16 + threadIdx.x;

    const float* Xg = X + ((size_t)b * NS + i0) * DD;
    const float* Yg = Y + ((size_t)b * NS + j0) * DD;

    float4* Xs4 = reinterpret_cast<float4*>(Xs);
    float4* Ys4 = reinterpret_cast<float4*>(Ys);

#pragma unroll
    for (int t = 0; t < 4; ++t) {
        int lin = t * 256 + tid;
        int row = lin >> 4;
        int k4  = lin & 15;
        int sw  = k4 ^ (row & 15);
        Xs4[row * 16 + sw] = *reinterpret_cast<const float4*>(Xg + row * DD + k4 * 4);
        Ys4[row * 16 + sw] = *reinterpret_cast<const float4*>(Yg + row * DD + k4 * 4);
    }
    __syncthreads();

    if (tid < 128) {
        int r = tid & 63;
        const float4* P = (tid < 64) ? reinterpret_cast<const float4*>(Xs)
                                     : reinterpret_cast<const float4*>(Ys);
        float s = 0.0f;
#pragma unroll
        for (int k4 = 0; k4 < 16; ++k4) {
            float4 v = P[r * 16 + (k4 ^ (r & 15))];
            s += v.x * v.x + v.y * v.y + v.z * v.z + v.w * v.w;
        }
        if (tid < 64) xn[r] = s; else yn[r] = s;
    }
    __syncthreads();

    const int tx = threadIdx.x, ty = threadIdx.y;

    unsigned long long acc[4][4];
#pragma unroll
    for (int r = 0; r < 4; ++r)
#pragma unroll
        for (int c = 0; c < 4; ++c) acc[r][c] = 0ull;

    const ulonglong2* Xs2 = reinterpret_cast<const ulonglong2*>(Xs);
    const ulonglong2* Ys2 = reinterpret_cast<const ulonglong2*>(Ys);

#pragma unroll
    for (int k4 = 0; k4 < 16; ++k4) {
        ulonglong2 av[4], bv[4];
#pragma unroll
        for (int r = 0; r < 4; ++r) {
            int i = ty + 16 * r;
            av[r] = Xs2[i * 16 + (k4 ^ (i & 15))];
        }
#pragma unroll
        for (int c = 0; c < 4; ++c) {
            int j = tx + 16 * c;
            bv[c] = Ys2[j * 16 + (k4 ^ (j & 15))];
        }
#pragma unroll
        for (int r = 0; r < 4; ++r)
#pragma unroll
            for (int c = 0; c < 4; ++c) {
                fma2(acc[r][c], av[r].x, bv[c].x);
                fma2(acc[r][c], av[r].y, bv[c].y);
            }
    }

    float* Eout = g_E + (size_t)b * NS * NS;
#pragma unroll
    for (int r = 0; r < 4; ++r) {
        int i = ty + 16 * r;
#pragma unroll
        for (int c = 0; c < 4; ++c) {
            int j = tx + 16 * c;
            float lo = __uint_as_float((unsigned)(acc[r][c] & 0xffffffffull));
            float hi = __uint_as_float((unsigned)(acc[r][c] >> 32));
            float d2 = xn[i] + yn[j] - 2.0f * (lo + hi);
            float dist = sqrtf(fmaxf(d2, 0.0f));
            Eout[(size_t)(i0 + i) * NS + (j0 + j)] =
                exp2f(-1.4426950408889634f * dist);
        }
    }
}

// ---------------------------------------------------------------------------
// Stage 2: weight-domain soft-DTW, binary scaling. 64 CTAs x 64 threads.
// Each thread owns TWO 4x8 tile-chains (tile-rows 2ti and 2ti+1); within a
// diagonal the two chains are independent -> 2x single-warp ILP. Only chain B
// touches SMEM; A->B handoff is register-resident.
// ---------------------------------------------------------------------------
__device__ __forceinline__ float exp2i_s(int e) {
    return (e >= -126) ? __int_as_float((e + 127) << 23) : 0.0f;
}
__device__ __forceinline__ int fexp(float m) {
    return ((__float_as_int(m) >> 23) & 0xff) - 127;
}

struct TileState {
    float left[4];       // renormed right-col outputs (next tile's left)
    int leftC2;
    float cornE;         // self-carried corner (own exponent)
    int cornC2;
    float4 o0, o1;       // renormed bottom-row outputs (mantissas)
    int oC2;             // their scale
    float lastRaw;       // pre-renorm prev[8] of final cell
    int lastC2;          // its scale
};

// Compute one 4x8 tile; top frontier passed in (t0,t1,sTop); outputs into st.
__device__ __forceinline__ void tile_step(
    TileState& st, int tj, int tileRow,
    float4 t0, float4 t1, int sTop, const float4 (&eb)[8])
{
    if (tj == 0) {   // activation reset (predicated)
        st.left[0] = st.left[1] = st.left[2] = st.left[3] = 0.0f;
        st.leftC2 = C2_NEG;
        st.cornE  = (tileRow == 0) ? 1.0f : 0.0f;
        st.cornC2 = (tileRow == 0) ? 0 : C2_NEG;
    }

    int c2 = max(max(sTop, st.cornC2), st.leftC2);
    const float ft = exp2i_s(sTop      - c2 + SHIFT);
    const float fc = exp2i_s(st.cornC2 - c2 + SHIFT);
    const float fl = exp2i_s(st.leftC2 - c2 + SHIFT);

    float prev[9];
    prev[0] = st.cornE * fc;
    prev[1] = t0.x * ft; prev[2] = t0.y * ft; prev[3] = t0.z * ft; prev[4] = t0.w * ft;
    prev[5] = t1.x * ft; prev[6] = t1.y * ft; prev[7] = t1.z * ft; prev[8] = t1.w * ft;
    float lE0 = st.left[0] * fl, lE1 = st.left[1] * fl,
          lE2 = st.left[2] * fl, lE3 = st.left[3] * fl;
    const float newCorn = prev[8];

    float right[4];
#pragma unroll
    for (int a = 0; a < 4; ++a) {
        const float4 eA = eb[2 * a], eB = eb[2 * a + 1];
        const float nl = (a == 0) ? lE0 : (a == 1) ? lE1 : (a == 2) ? lE2 : lE3;
        float carry = prev[0];
        prev[0] = nl;
        float s;
        s = (carry + prev[1]) + prev[0]; carry = prev[1]; prev[1] = eA.x * s;
        s = (carry + prev[2]) + prev[1]; carry = prev[2]; prev[2] = eA.y * s;
        s = (carry + prev[3]) + prev[2]; carry = prev[3]; prev[3] = eA.z * s;
        s = (carry + prev[4]) + prev[3]; carry = prev[4]; prev[4] = eA.w * s;
        s = (carry + prev[5]) + prev[4]; carry = prev[5]; prev[5] = eB.x * s;
        s = (carry + prev[6]) + prev[5]; carry = prev[6]; prev[6] = eB.y * s;
        s = (carry + prev[7]) + prev[6]; carry = prev[7]; prev[7] = eB.z * s;
        s = (carry + prev[8]) + prev[7];                  prev[8] = eB.w * s;
        right[a] = prev[8];
    }

    st.lastRaw = prev[8];
    st.lastC2  = c2 - SHIFT;

    // Merged renorm of the 12 outputs.
    float m = fmaxf(fmaxf(fmaxf(prev[1], prev[2]), fmaxf(prev[3], prev[4])),
                    fmaxf(fmaxf(prev[5], prev[6]), fmaxf(prev[7], prev[8])));
    m = fmaxf(m, fmaxf(fmaxf(right[0], right[1]), fmaxf(right[2], right[3])));
    int em = fexp(m);
    float rs = __int_as_float((127 - em) << 23);
    int c2n = (m > 0.0f) ? (c2 - SHIFT + em) : C2_NEG;

    st.o0 = make_float4(prev[1] * rs, prev[2] * rs, prev[3] * rs, prev[4] * rs);
    st.o1 = make_float4(prev[5] * rs, prev[6] * rs, prev[7] * rs, prev[8] * rs);
    st.oC2 = c2n;
    st.left[0] = right[0] * rs; st.left[1] = right[1] * rs;
    st.left[2] = right[2] * rs; st.left[3] = right[3] * rs;
    st.leftC2 = c2n;

    int ec = fexp(newCorn);
    st.cornE  = newCorn * __int_as_float((127 - ec) << 23);
    st.cornC2 = (newCorn > 0.0f) ? (c2 - SHIFT + ec) : C2_NEG;
}

__device__ __forceinline__ int clampj(int t) {
    return (t < 0) ? 0 : (t > GTJ - 1 ? GTJ - 1 : t);
}

__device__ __forceinline__ void prefetch8(const float* __restrict__ base,
                                          int tjn, float4 (&nb)[8]) {
    int c8 = clampj(tjn) * 8;
#pragma unroll
    for (int a = 0; a < 4; ++a) {
        nb[2 * a]     = *reinterpret_cast<const float4*>(base + a * NS + c8);
        nb[2 * a + 1] = *reinterpret_cast<const float4*>(base + a * NS + c8 + 4);
    }
}

__device__ __forceinline__ void dp_step(
    int kd, int ti, int b,
    const float* __restrict__ ErowA, const float* __restrict__ ErowB,
    const float4 (&cbA)[8], float4 (&nbA)[8],
    const float4 (&cbB)[8], float4 (&nbB)[8],
    float4 (*rowE4)[2 * GTJ + 2], int (*rowC2)[GTJ + 2],
    TileState& A, TileState& B, float* __restrict__ out)
{
    const int tjA = kd - 2 * ti;
    const int tjB = tjA - 1;
    const int wb  = kd & 1, rb = wb ^ 1;
    const int tjrA = clampj(tjA);

    // A's top frontier from SMEM (thread ti-1's B, previous diagonal;
    // pristine pre-zeroed slots provide the row -1 / not-yet-written boundary).
    float4 t0A = rowE4[rb][2 * tjrA];
    float4 t1A = rowE4[rb][2 * tjrA + 1];
    int   sTopA = rowC2[rb][tjrA];

    // B's top frontier = A's previous-diagonal outputs (registers).
    float4 t0B = A.o0, t1B = A.o1;
    int   sTopB = A.oC2;

    // Prefetch next diagonal's tiles (always issued, clamped).
    prefetch8(ErowA, tjA + 1, nbA);
    prefetch8(ErowB, tjB + 1, nbB);

    // Two independent 4x8 chains (B first: register inputs, starts immediately).
    tile_step(B, tjB, 2 * ti + 1, t0B, t1B, sTopB, cbB);
    tile_step(A, tjA, 2 * ti,     t0A, t1A, sTopA, cbA);

    // Final cell of the DP: tile-row 127 = B of thread 63, column 63.
    if (tjB == GTJ - 1 && ti == 63)
        out[b] = -(log2f(B.lastRaw) + (float)B.lastC2) * 0.69314718055994530942f;

    // Only B publishes to SMEM (for thread ti+1's A).
    const bool actB = (unsigned)tjB < (unsigned)GTJ;
    const int ws = actB ? 2 * tjB : 2 * GTJ;
    rowE4[wb][ws]     = B.o0;
    rowE4[wb][ws + 1] = B.o1;
    rowC2[wb][actB ? tjB : GTJ] = B.oC2;
    __syncthreads();
}

__global__ void __launch_bounds__(64, 1)
dp_kernel(float* __restrict__ out) {
    const int b = blockIdx.x;
    const float* Eb = g_E + (size_t)b * NS * NS;

    __shared__ __align__(16) float4 rowE4[2][2 * GTJ + 2];
    __shared__ int rowC2[2][GTJ + 2];

    const int ti = threadIdx.x;                   // 0..63
    const float* ErowA = Eb + (size_t)(8 * ti) * NS;
    const float* ErowB = Eb + (size_t)(8 * ti + 4) * NS;

    // Pre-zero both parities (boundary: W = 0, scale C2_NEG).
    {
        float4 z = make_float4(0.f, 0.f, 0.f, 0.f);
        float4* re = &rowE4[0][0];
        for (int s = ti; s < 2 * (2 * GTJ + 2); s += 64) re[s] = z;
        int* rc = &rowC2[0][0];
        for (int s = ti; s < 2 * (GTJ + 2); s += 64) rc[s] = C2_NEG;
    }

    float4 bA0[8], bA1[8], bB0[8], bB1[8];
    prefetch8(ErowA, 0, bA0);     // tile tjA = 0 (consumed by ti=0 at kd=0)
    prefetch8(ErowB, 0, bB0);
#pragma unroll
    for (int a = 0; a < 8; ++a) { bA1[a] = bA0[a]; bB1[a] = bB0[a]; }

    TileState A, B;
    A.left[0] = A.left[1] = A.left[2] = A.left[3] = 0.f;
    A.leftC2 = C2_NEG; A.cornE = 0.f; A.cornC2 = C2_NEG;
    A.o0 = make_float4(0.f, 0.f, 0.f, 0.f); A.o1 = A.o0; A.oC2 = C2_NEG;
    A.lastRaw = 0.f; A.lastC2 = C2_NEG;
    B = A;

    __syncthreads();

    for (int kd = 0; kd < NDIAG; kd += 2) {
        dp_step(kd,     ti, b, ErowA, ErowB, bA0, bA1, bB0, bB1,
                rowE4, rowC2, A, B, out);
        dp_step(kd + 1, ti, b, ErowA, ErowB, bA1, bA0, bB1, bB0,
                rowE4, rowC2, A, B, out);
    }
}

// ---------------------------------------------------------------------------
extern "C" void kernel_launch(void* const* d_in, const int* in_sizes, int n_in,
                              void* d_out, int out_size) {
    (void)in_sizes; (void)n_in; (void)out_size;
    const float* X = (const float*)d_in[0];
    const float* Y = (const float*)d_in[1];
    float* out = (float*)d_out;

    dim3 g1(NS / 64, NS / 64, NB);   // (8, 8, 64)
    dim3 b1(16, 16);
    cdist_kernel<<<g1, b1>>>(X, Y);

    dp_kernel<<<NB, 64>>>(out);
}